// round 1
// baseline (speedup 1.0000x reference)
#include <cuda_runtime.h>

#define N_NODES 100000
#define N_EDGES 1000000
#define IN_V 16
#define OUT_V 16
#define IN_E 4

__device__ float g_t[N_NODES * 64];    // [n][o][c]  t[n,o,c] = sum_i v[n,i]*W[i*16+o][c]
__device__ float g_tb[N_NODES * 16];   // [n][o]     tb[n,o] = sum_i v[n,i]*b[i*16+o]
__device__ float g_sum[N_NODES * 16];  // scatter accumulator
__device__ float g_cnt[N_NODES];       // degree accumulator
__device__ float g_s1[16];             // batch sum per feature
__device__ float g_s2[16];             // batch sum of squares per feature

// ---------------------------------------------------------------------------
// K0: zero accumulators
// ---------------------------------------------------------------------------
__global__ void __launch_bounds__(256) k_zero() {
    int idx = blockIdx.x * blockDim.x + threadIdx.x;
    int stride = gridDim.x * blockDim.x;
    for (int i = idx; i < N_NODES * 16; i += stride) g_sum[i] = 0.0f;
    for (int i = idx; i < N_NODES; i += stride) g_cnt[i] = 0.0f;
    if (idx < 16) { g_s1[idx] = 0.0f; g_s2[idx] = 0.0f; }
}

// ---------------------------------------------------------------------------
// K1: per-node precompute of t and tb.
// One thread per (node, o): 16 nodes x 16 o per 256-thread block.
// ---------------------------------------------------------------------------
__global__ void __launch_bounds__(256) k_node_pre(
    const float* __restrict__ v,
    const float* __restrict__ enet_w,   // [256][4]
    const float* __restrict__ enet_b)   // [256]
{
    __shared__ float sw[1024];
    __shared__ float sb[256];
    int t = threadIdx.x;
    for (int i = t; i < 1024; i += 256) sw[i] = enet_w[i];
    sb[t] = enet_b[t];
    __syncthreads();

    int gid = blockIdx.x * 256 + t;
    int n = gid >> 4;
    int o = gid & 15;
    if (n >= N_NODES) return;

    float a0 = 0.f, a1 = 0.f, a2 = 0.f, a3 = 0.f, ab = 0.f;
    const float* vrow = v + n * 16;
#pragma unroll
    for (int i = 0; i < 16; i++) {
        float vi = vrow[i];
        int j = i * 16 + o;
        const float* w4 = sw + j * 4;
        a0 = fmaf(vi, w4[0], a0);
        a1 = fmaf(vi, w4[1], a1);
        a2 = fmaf(vi, w4[2], a2);
        a3 = fmaf(vi, w4[3], a3);
        ab = fmaf(vi, sb[j], ab);
    }
    *reinterpret_cast<float4*>(g_t + (size_t)n * 64 + o * 4) = make_float4(a0, a1, a2, a3);
    g_tb[n * 16 + o] = ab;
}

// ---------------------------------------------------------------------------
// K2: per-edge message + vector RED scatter.
// 4 threads per edge; thread j handles outputs o = 4j..4j+3.
// msg[o] = sum_c e[c] * t[src,o,c] + tb[src,o]
// ---------------------------------------------------------------------------
__global__ void __launch_bounds__(256) k_edge(
    const float* __restrict__ efeat,
    const int* __restrict__ ei)   // [2][E] row0=src, row1=dst
{
    int gid = blockIdx.x * blockDim.x + threadIdx.x;
    int eid = gid >> 2;
    int j = gid & 3;
    if (eid >= N_EDGES) return;

    int src = ei[eid];
    int dst = ei[N_EDGES + eid];

    float4 ev = *reinterpret_cast<const float4*>(efeat + (size_t)eid * 4);
    const float4* tp = reinterpret_cast<const float4*>(g_t + (size_t)src * 64 + j * 16);
    float4 t0 = tp[0], t1 = tp[1], t2 = tp[2], t3 = tp[3];
    float4 tb4 = *reinterpret_cast<const float4*>(g_tb + (size_t)src * 16 + j * 4);

    float m0 = fmaf(ev.x, t0.x, fmaf(ev.y, t0.y, fmaf(ev.z, t0.z, fmaf(ev.w, t0.w, tb4.x))));
    float m1 = fmaf(ev.x, t1.x, fmaf(ev.y, t1.y, fmaf(ev.z, t1.z, fmaf(ev.w, t1.w, tb4.y))));
    float m2 = fmaf(ev.x, t2.x, fmaf(ev.y, t2.y, fmaf(ev.z, t2.z, fmaf(ev.w, t2.w, tb4.z))));
    float m3 = fmaf(ev.x, t3.x, fmaf(ev.y, t3.y, fmaf(ev.z, t3.z, fmaf(ev.w, t3.w, tb4.w))));

    float* outp = g_sum + (size_t)dst * 16 + j * 4;
    asm volatile("red.global.add.v4.f32 [%0], {%1, %2, %3, %4};"
                 :: "l"(outp), "f"(m0), "f"(m1), "f"(m2), "f"(m3)
                 : "memory");
    if (j == 0) atomicAdd(g_cnt + dst, 1.0f);
}

// ---------------------------------------------------------------------------
// K3: finalize pre-BN output + accumulate batch stats.
// out_pre[n,o] = g_sum[n,o]/max(cnt,1) + sum_i v[n,i]*root[i,o] + bias[o]
// ---------------------------------------------------------------------------
__global__ void __launch_bounds__(256) k_final(
    const float* __restrict__ v,
    const float* __restrict__ root,   // [16][16] (i,o)
    const float* __restrict__ bias,   // [16]
    float* __restrict__ out)
{
    __shared__ float sroot[256];
    __shared__ float sv[256];
    __shared__ float r1[256];
    __shared__ float r2[256];
    int t = threadIdx.x;
    sroot[t] = root[t];
    int o = t & 15;
    int nl = t >> 4;
    float sb = bias[o];

    float ls1 = 0.0f, ls2 = 0.0f;
    const int ntiles = N_NODES / 16;   // 6250 exact
    for (int tile = blockIdx.x; tile < ntiles; tile += gridDim.x) {
        int nbase = tile * 16;
        __syncthreads();
        sv[t] = v[nbase * 16 + t];
        __syncthreads();
        float acc = sb;
#pragma unroll
        for (int i = 0; i < 16; i++)
            acc = fmaf(sv[nl * 16 + i], sroot[i * 16 + o], acc);
        int n = nbase + nl;
        float cnt = g_cnt[n];
        float val = g_sum[n * 16 + o] / fmaxf(cnt, 1.0f) + acc;
        out[n * 16 + o] = val;
        ls1 += val;
        ls2 = fmaf(val, val, ls2);
    }

    r1[t] = ls1;
    r2[t] = ls2;
    __syncthreads();
#pragma unroll
    for (int s = 128; s >= 16; s >>= 1) {
        if (t < s) { r1[t] += r1[t + s]; r2[t] += r2[t + s]; }
        __syncthreads();
    }
    if (t < 16) {
        atomicAdd(&g_s1[t], r1[t]);
        atomicAdd(&g_s2[t], r2[t]);
    }
}

// ---------------------------------------------------------------------------
// K4: BatchNorm (batch stats) + LeakyReLU, in-place on out.
// ---------------------------------------------------------------------------
__global__ void __launch_bounds__(256) k_bn(
    float* __restrict__ out,
    const float* __restrict__ gamma,
    const float* __restrict__ beta)
{
    int idx = blockIdx.x * blockDim.x + threadIdx.x;
    if (idx >= N_NODES * 16) return;
    int o = idx & 15;
    const float invN = 1.0f / (float)N_NODES;
    float mu = g_s1[o] * invN;
    float var = g_s2[o] * invN - mu * mu;
    float val = out[idx];
    val = gamma[o] * (val - mu) * rsqrtf(var + 1e-5f) + beta[o];
    out[idx] = (val >= 0.0f) ? val : 0.01f * val;
}

// ---------------------------------------------------------------------------
extern "C" void kernel_launch(void* const* d_in, const int* in_sizes, int n_in,
                              void* d_out, int out_size) {
    const float* v      = (const float*)d_in[0];
    const float* e      = (const float*)d_in[1];
    const int*   ei     = (const int*)  d_in[2];
    const float* enet_w = (const float*)d_in[3];
    const float* enet_b = (const float*)d_in[4];
    const float* root   = (const float*)d_in[5];
    const float* bias   = (const float*)d_in[6];
    const float* gamma  = (const float*)d_in[7];
    const float* beta   = (const float*)d_in[8];
    float* out = (float*)d_out;

    k_zero<<<832, 256>>>();
    k_node_pre<<<(N_NODES * 16 + 255) / 256, 256>>>(v, enet_w, enet_b);
    k_edge<<<(N_EDGES * 4 + 255) / 256, 256>>>(e, ei);
    k_final<<<740, 256>>>(v, root, bias, out);
    k_bn<<<(N_NODES * 16 + 255) / 256, 256>>>(out, gamma, beta);
}

// round 2
// speedup vs baseline: 1.4092x; 1.4092x over previous
#include <cuda_runtime.h>
#include <cuda_fp16.h>

#define N_NODES 100000
#define N_EDGES 1000000

__device__ __half g_t[N_NODES * 64];    // [n][o][c] fp16: t[n,o,c] = sum_i v[n,i]*W[i*16+o][c]
__device__ __half g_tb[N_NODES * 16];   // [n][o]    fp16: tb[n,o] = sum_i v[n,i]*b[i*16+o]
__device__ float  g_r[N_NODES * 16];    // [n][o]    fp32: v@root + bias (node-local term)
__device__ float  g_sum[N_NODES * 16];  // scatter accumulator
__device__ float  g_cnt[N_NODES];       // degree accumulator
__device__ float  g_s1[16];             // batch sum per feature
__device__ float  g_s2[16];             // batch sum-of-squares per feature

// ---------------------------------------------------------------------------
// K0: zero accumulators (float4 stores)
// ---------------------------------------------------------------------------
__global__ void __launch_bounds__(256) k_zero() {
    int idx = blockIdx.x * blockDim.x + threadIdx.x;
    int stride = gridDim.x * blockDim.x;
    float4* s4 = reinterpret_cast<float4*>(g_sum);
    const float4 z = make_float4(0.f, 0.f, 0.f, 0.f);
    for (int i = idx; i < N_NODES * 4; i += stride) s4[i] = z;
    for (int i = idx; i < N_NODES; i += stride) g_cnt[i] = 0.0f;
    if (idx < 16) { g_s1[idx] = 0.0f; g_s2[idx] = 0.0f; }
}

// ---------------------------------------------------------------------------
// K1: per-node precompute of t (fp16), tb (fp16), and r = v@root + bias (fp32).
// 256 threads handle 16 nodes x 16 outputs; v rows staged through shared.
// ---------------------------------------------------------------------------
__global__ void __launch_bounds__(256) k_node_pre(
    const float* __restrict__ v,
    const float* __restrict__ enet_w,   // [256][4]
    const float* __restrict__ enet_b,   // [256]
    const float* __restrict__ root,     // [16][16] (i,o)
    const float* __restrict__ bias)     // [16]
{
    __shared__ float sw[1024];
    __shared__ float sb[256];
    __shared__ float sroot[256];
    __shared__ float sv[256];
    int t = threadIdx.x;
    for (int i = t; i < 1024; i += 256) sw[i] = enet_w[i];
    sb[t] = enet_b[t];
    sroot[t] = root[t];
    int nbase = blockIdx.x * 16;
    sv[t] = v[nbase * 16 + t];          // 16 node rows, coalesced
    __syncthreads();

    int nl = t >> 4;
    int o = t & 15;
    int n = nbase + nl;
    if (n >= N_NODES) return;

    float a0 = 0.f, a1 = 0.f, a2 = 0.f, a3 = 0.f, ab = 0.f, ar = bias[o];
    const float* vrow = sv + nl * 16;
#pragma unroll
    for (int i = 0; i < 16; i++) {
        float vi = vrow[i];
        int j = i * 16 + o;
        const float* w4 = sw + j * 4;
        a0 = fmaf(vi, w4[0], a0);
        a1 = fmaf(vi, w4[1], a1);
        a2 = fmaf(vi, w4[2], a2);
        a3 = fmaf(vi, w4[3], a3);
        ab = fmaf(vi, sb[j], ab);
        ar = fmaf(vi, sroot[j], ar);
    }
    // store 4 halfs (8B) at g_t[n*64 + o*4]
    __half2 h01 = __floats2half2_rn(a0, a1);
    __half2 h23 = __floats2half2_rn(a2, a3);
    uint2 pk;
    pk.x = *reinterpret_cast<unsigned*>(&h01);
    pk.y = *reinterpret_cast<unsigned*>(&h23);
    *reinterpret_cast<uint2*>(g_t + (size_t)n * 64 + o * 4) = pk;
    g_tb[n * 16 + o] = __float2half_rn(ab);
    g_r[n * 16 + o] = ar;
}

// ---------------------------------------------------------------------------
// K2: per-edge message + vector RED scatter.
// 4 threads per edge; thread j handles outputs o = 4j..4j+3.
// msg[o] = sum_c e[c] * t[src,o,c] + tb[src,o]
// ---------------------------------------------------------------------------
__global__ void __launch_bounds__(256) k_edge(
    const float* __restrict__ efeat,
    const int* __restrict__ ei)   // [2][E] row0=src, row1=dst
{
    int gid = blockIdx.x * blockDim.x + threadIdx.x;
    int eid = gid >> 2;
    int j = gid & 3;
    if (eid >= N_EDGES) return;

    int src = ei[eid];
    int dst = ei[N_EDGES + eid];

    float4 ev = *reinterpret_cast<const float4*>(efeat + (size_t)eid * 4);

    // 16 halfs: t[src, 4j+0..3, 0..3]  (two 16B loads, 32B aligned)
    const __half2* tp = reinterpret_cast<const __half2*>(g_t + (size_t)src * 64 + j * 16);
    __half2 h[8];
    *reinterpret_cast<uint4*>(&h[0]) = *reinterpret_cast<const uint4*>(tp);
    *reinterpret_cast<uint4*>(&h[4]) = *reinterpret_cast<const uint4*>(tp + 4);

    // 4 halfs tb (8B)
    uint2 tbp = *reinterpret_cast<const uint2*>(g_tb + (size_t)src * 16 + j * 4);
    __half2 tb01 = *reinterpret_cast<__half2*>(&tbp.x);
    __half2 tb23 = *reinterpret_cast<__half2*>(&tbp.y);
    float2 tbf0 = __half22float2(tb01);
    float2 tbf1 = __half22float2(tb23);

    float2 c01, c23;
    c01 = __half22float2(h[0]); c23 = __half22float2(h[1]);
    float m0 = fmaf(ev.x, c01.x, fmaf(ev.y, c01.y, fmaf(ev.z, c23.x, fmaf(ev.w, c23.y, tbf0.x))));
    c01 = __half22float2(h[2]); c23 = __half22float2(h[3]);
    float m1 = fmaf(ev.x, c01.x, fmaf(ev.y, c01.y, fmaf(ev.z, c23.x, fmaf(ev.w, c23.y, tbf0.y))));
    c01 = __half22float2(h[4]); c23 = __half22float2(h[5]);
    float m2 = fmaf(ev.x, c01.x, fmaf(ev.y, c01.y, fmaf(ev.z, c23.x, fmaf(ev.w, c23.y, tbf1.x))));
    c01 = __half22float2(h[6]); c23 = __half22float2(h[7]);
    float m3 = fmaf(ev.x, c01.x, fmaf(ev.y, c01.y, fmaf(ev.z, c23.x, fmaf(ev.w, c23.y, tbf1.y))));

    float* outp = g_sum + (size_t)dst * 16 + j * 4;
    asm volatile("red.global.add.v4.f32 [%0], {%1, %2, %3, %4};"
                 :: "l"(outp), "f"(m0), "f"(m1), "f"(m2), "f"(m3)
                 : "memory");
    if (j == 0) atomicAdd(g_cnt + dst, 1.0f);
}

// ---------------------------------------------------------------------------
// K3: finalize pre-BN output (pure streaming, float4) + accumulate batch stats.
// out[n,o] = g_sum[n,o]/max(cnt,1) + g_r[n,o]
// ---------------------------------------------------------------------------
__global__ void __launch_bounds__(256) k_final(float* __restrict__ out)
{
    int t = threadIdx.x;
    int idx = blockIdx.x * 256 + t;
    int stride = gridDim.x * 256;          // multiple of 4 => (idx&3) invariant
    const float4* s4 = reinterpret_cast<const float4*>(g_sum);
    const float4* r4 = reinterpret_cast<const float4*>(g_r);
    float4* o4 = reinterpret_cast<float4*>(out);

    float s1x = 0.f, s1y = 0.f, s1z = 0.f, s1w = 0.f;
    float s2x = 0.f, s2y = 0.f, s2z = 0.f, s2w = 0.f;

    for (int i = idx; i < N_NODES * 4; i += stride) {
        int n = i >> 2;
        float inv = 1.0f / fmaxf(g_cnt[n], 1.0f);
        float4 s = s4[i];
        float4 r = r4[i];
        float4 val;
        val.x = fmaf(s.x, inv, r.x);
        val.y = fmaf(s.y, inv, r.y);
        val.z = fmaf(s.z, inv, r.z);
        val.w = fmaf(s.w, inv, r.w);
        o4[i] = val;
        s1x += val.x; s1y += val.y; s1z += val.z; s1w += val.w;
        s2x = fmaf(val.x, val.x, s2x);
        s2y = fmaf(val.y, val.y, s2y);
        s2z = fmaf(val.z, val.z, s2z);
        s2w = fmaf(val.w, val.w, s2w);
    }

    // warp reduction over lanes with the same (lane&3): xor 4, 8, 16
#pragma unroll
    for (int m = 4; m <= 16; m <<= 1) {
        s1x += __shfl_xor_sync(0xffffffffu, s1x, m);
        s1y += __shfl_xor_sync(0xffffffffu, s1y, m);
        s1z += __shfl_xor_sync(0xffffffffu, s1z, m);
        s1w += __shfl_xor_sync(0xffffffffu, s1w, m);
        s2x += __shfl_xor_sync(0xffffffffu, s2x, m);
        s2y += __shfl_xor_sync(0xffffffffu, s2y, m);
        s2z += __shfl_xor_sync(0xffffffffu, s2z, m);
        s2w += __shfl_xor_sync(0xffffffffu, s2w, m);
    }

    __shared__ float sm1[8][4][4];
    __shared__ float sm2[8][4][4];
    int warp = t >> 5;
    int lane = t & 31;
    if (lane < 4) {   // lane = jpos group; o = 4*lane + comp
        sm1[warp][lane][0] = s1x; sm1[warp][lane][1] = s1y;
        sm1[warp][lane][2] = s1z; sm1[warp][lane][3] = s1w;
        sm2[warp][lane][0] = s2x; sm2[warp][lane][1] = s2y;
        sm2[warp][lane][2] = s2z; sm2[warp][lane][3] = s2w;
    }
    __syncthreads();
    if (t < 16) {   // o = t;  jpos = t>>2, comp = t&3
        float a1 = 0.f, a2 = 0.f;
#pragma unroll
        for (int w = 0; w < 8; w++) {
            a1 += sm1[w][t >> 2][t & 3];
            a2 += sm2[w][t >> 2][t & 3];
        }
        atomicAdd(&g_s1[t], a1);
        atomicAdd(&g_s2[t], a2);
    }
}

// ---------------------------------------------------------------------------
// K4: BatchNorm (batch stats) + LeakyReLU, float4 in-place.
// ---------------------------------------------------------------------------
__global__ void __launch_bounds__(256) k_bn(
    float* __restrict__ out,
    const float* __restrict__ gamma,
    const float* __restrict__ beta)
{
    int i = blockIdx.x * blockDim.x + threadIdx.x;
    if (i >= N_NODES * 4) return;
    int ob = (i & 3) * 4;
    const float invN = 1.0f / (float)N_NODES;

    float4* o4 = reinterpret_cast<float4*>(out);
    float4 val = o4[i];
    float g0, b0, m0, vv0;
    float res[4];
    float vin[4] = {val.x, val.y, val.z, val.w};
#pragma unroll
    for (int k = 0; k < 4; k++) {
        int o = ob + k;
        m0 = g_s1[o] * invN;
        vv0 = g_s2[o] * invN - m0 * m0;
        g0 = gamma[o]; b0 = beta[o];
        float x = g0 * (vin[k] - m0) * rsqrtf(vv0 + 1e-5f) + b0;
        res[k] = (x >= 0.0f) ? x : 0.01f * x;
    }
    o4[i] = make_float4(res[0], res[1], res[2], res[3]);
}

// ---------------------------------------------------------------------------
extern "C" void kernel_launch(void* const* d_in, const int* in_sizes, int n_in,
                              void* d_out, int out_size) {
    const float* v      = (const float*)d_in[0];
    const float* e      = (const float*)d_in[1];
    const int*   ei     = (const int*)  d_in[2];
    const float* enet_w = (const float*)d_in[3];
    const float* enet_b = (const float*)d_in[4];
    const float* root   = (const float*)d_in[5];
    const float* bias   = (const float*)d_in[6];
    const float* gamma  = (const float*)d_in[7];
    const float* beta   = (const float*)d_in[8];
    float* out = (float*)d_out;

    k_zero<<<592, 256>>>();
    k_node_pre<<<(N_NODES + 15) / 16, 256>>>(v, enet_w, enet_b, root, bias);
    k_edge<<<(N_EDGES * 4 + 255) / 256, 256>>>(e, ei);
    k_final<<<592, 256>>>(out);
    k_bn<<<(N_NODES * 4 + 255) / 256, 256>>>(out, gamma, beta);
}